// round 14
// baseline (speedup 1.0000x reference)
#include <cuda_runtime.h>
#include <cuda_fp16.h>
#include <cstdint>
#include <math.h>

#define NN 50000
#define NE 800000
#define HID 128
#define NG 500

// Scratch (device globals: no allocation allowed)
__device__ float g_h[(size_t)NN * HID];
__device__ __half g_Ph[(size_t)NN * 512];       // [Fdst|Sdst|Fsrc|Ssrc] per node (fp16)
__device__ float g_agg[(size_t)NN * HID];
__device__ float g_pool[NG * HID];
__device__ float g_cnt[NG];

// ---------------------------------------------------------------------------
// helpers
// ---------------------------------------------------------------------------
__device__ __forceinline__ uint32_t f2tf32(float x) {
    uint32_t u;
    asm("cvt.rna.tf32.f32 %0, %1;" : "=r"(u) : "f"(x));
    return u;
}

__device__ __forceinline__ void mma_tf32(float c[4], const uint32_t a[4],
                                         const uint32_t b[2]) {
    asm volatile(
        "mma.sync.aligned.m16n8k8.row.col.f32.tf32.tf32.f32 "
        "{%0,%1,%2,%3}, {%4,%5,%6,%7}, {%8,%9}, {%0,%1,%2,%3};"
        : "+f"(c[0]), "+f"(c[1]), "+f"(c[2]), "+f"(c[3])
        : "r"(a[0]), "r"(a[1]), "r"(a[2]), "r"(a[3]), "r"(b[0]), "r"(b[1]));
}

__device__ __forceinline__ float sigmoidf_(float x) {
    return __fdividef(1.f, 1.f + __expf(-x));
}
__device__ __forceinline__ float softplusf_(float x) {
    return fmaxf(x, 0.f) + __logf(1.f + __expf(-fabsf(x)));
}

__device__ __forceinline__ void red4(float* p, float a, float b, float c, float d) {
    asm volatile("red.global.add.v4.f32 [%0], {%1,%2,%3,%4};"
                 :: "l"(p), "f"(a), "f"(b), "f"(c), "f"(d) : "memory");
}

// ---------------------------------------------------------------------------
// init: h = emb[x]; zero agg/pool/cnt
// ---------------------------------------------------------------------------
__global__ void k_init(const int* __restrict__ x, const float* __restrict__ emb) {
    int idx = blockIdx.x * blockDim.x + threadIdx.x;  // over NN*32
    if (idx < NN * 32) {
        int n = idx >> 5, q = idx & 31;
        ((float4*)g_h)[idx] = ((const float4*)emb)[x[n] * 32 + q];
        ((float4*)g_agg)[idx] = make_float4(0.f, 0.f, 0.f, 0.f);
    }
    if (idx < NG * 32) ((float4*)g_pool)[idx] = make_float4(0.f, 0.f, 0.f, 0.f);
    if (idx < NG) g_cnt[idx] = 0.f;
}

// ---------------------------------------------------------------------------
// Node GEMM, all 4 kinds per CTA (tf32 mma, double-buffered B slabs).
// ---------------------------------------------------------------------------
#define ASTR3 136
#define BSTR3 136
#define SMEM_GEMM ((128 * ASTR3 + 2 * 32 * BSTR3) * 4)

extern __shared__ unsigned char s_raw[];

__global__ void __launch_bounds__(256, 2)
k_gemm_all(float* __restrict__ Ah, float* __restrict__ Agg, int fuse,
           const float* __restrict__ Wf, const float* __restrict__ Ws,
           const float* __restrict__ bf, const float* __restrict__ bs,
           __half* __restrict__ out)
{
    uint32_t* Ast = (uint32_t*)s_raw;          // [128 m][ASTR3]
    uint32_t* Bs  = Ast + 128 * ASTR3;         // [2][32 k][BSTR3]

    int row0 = blockIdx.x * 128;
    int tid = threadIdx.x;
    int lane = tid & 31, wid = tid >> 5;
    int wm = (wid & 1) * 64, wn = (wid >> 1) * 32;
    int gid4 = lane >> 2, tig = lane & 3;

    float4 pre[4];
    auto fetch = [&](int iter) {
        int kind = iter >> 2, slab = iter & 3;
        const float* W = (kind & 1) ? Ws : Wf;
        const float* base = W + (size_t)(((kind >> 1) ? 128 : 0) + slab * 32) * 128;
#pragma unroll
        for (int i = 0; i < 4; i++) {
            int id = tid + i * 256;
            int kk = id >> 5, c4 = (id & 31) * 4;
            pre[i] = *(const float4*)(base + kk * 128 + c4);
        }
    };
    auto commit = [&](int buf) {
#pragma unroll
        for (int i = 0; i < 4; i++) {
            int id = tid + i * 256;
            int kk = id >> 5, c4 = (id & 31) * 4;
            uint32_t* d = &Bs[(buf * 32 + kk) * BSTR3 + c4];
            d[0] = f2tf32(pre[i].x); d[1] = f2tf32(pre[i].y);
            d[2] = f2tf32(pre[i].z); d[3] = f2tf32(pre[i].w);
        }
    };

    fetch(0);

#pragma unroll
    for (int i = 0; i < 16; i++) {
        int id = tid + i * 256;
        int r = id >> 5, c4 = (id & 31) * 4;
        int gr = row0 + r;
        float4 v = make_float4(0.f, 0.f, 0.f, 0.f);
        if (gr < NN) {
            v = *(const float4*)(Ah + (size_t)gr * HID + c4);
            if (fuse) {
                float4 a = *(const float4*)(Agg + (size_t)gr * HID + c4);
                v.x = fmaxf(v.x + a.x, 0.f);
                v.y = fmaxf(v.y + a.y, 0.f);
                v.z = fmaxf(v.z + a.z, 0.f);
                v.w = fmaxf(v.w + a.w, 0.f);
                *(float4*)(Ah + (size_t)gr * HID + c4) = v;
                *(float4*)(Agg + (size_t)gr * HID + c4) = make_float4(0.f, 0.f, 0.f, 0.f);
            }
        }
        *(uint4*)&Ast[r * ASTR3 + c4] =
            make_uint4(f2tf32(v.x), f2tf32(v.y), f2tf32(v.z), f2tf32(v.w));
    }

    commit(0);
    __syncthreads();

    float acc[4][4][4];
#pragma unroll
    for (int i = 0; i < 4; i++)
#pragma unroll
        for (int j = 0; j < 4; j++)
#pragma unroll
            for (int r = 0; r < 4; r++) acc[i][j][r] = 0.f;

    for (int iter = 0; iter < 16; iter++) {
        if (iter < 15) fetch(iter + 1);
        int buf = iter & 1;
        int kbase = (iter & 3) * 32;

#pragma unroll
        for (int kk = 0; kk < 32; kk += 8) {
            uint32_t a[4][4], b[4][2];
#pragma unroll
            for (int i = 0; i < 4; i++) {
                int m0 = wm + i * 16 + gid4;
                const uint32_t* r0p = &Ast[m0 * ASTR3 + kbase + kk + tig];
                const uint32_t* r1p = &Ast[(m0 + 8) * ASTR3 + kbase + kk + tig];
                a[i][0] = r0p[0];
                a[i][1] = r1p[0];
                a[i][2] = r0p[4];
                a[i][3] = r1p[4];
            }
#pragma unroll
            for (int j = 0; j < 4; j++) {
                int n0 = wn + j * 8 + gid4;
                b[j][0] = Bs[(buf * 32 + kk + tig) * BSTR3 + n0];
                b[j][1] = Bs[(buf * 32 + kk + tig + 4) * BSTR3 + n0];
            }
#pragma unroll
            for (int i = 0; i < 4; i++)
#pragma unroll
                for (int j = 0; j < 4; j++) mma_tf32(acc[i][j], a[i], b[j]);
        }

        if ((iter & 3) == 3) {
            int kind = iter >> 2;
            const float* bias = (kind == 0) ? bf : (kind == 1) ? bs : nullptr;
            int cb = kind * 128;
#pragma unroll
            for (int j = 0; j < 4; j++) {
                int cl = wn + j * 8 + 2 * tig;
                float bx = 0.f, by = 0.f;
                if (bias) { bx = bias[cl]; by = bias[cl + 1]; }
#pragma unroll
                for (int i = 0; i < 4; i++) {
                    int r0 = row0 + wm + i * 16 + gid4;
                    if (r0 < NN)
                        *(__half2*)(out + (size_t)r0 * 512 + cb + cl) =
                            __floats2half2_rn(acc[i][j][0] + bx, acc[i][j][1] + by);
                    if (r0 + 8 < NN)
                        *(__half2*)(out + (size_t)(r0 + 8) * 512 + cb + cl) =
                            __floats2half2_rn(acc[i][j][2] + bx, acc[i][j][3] + by);
                }
            }
#pragma unroll
            for (int i = 0; i < 4; i++)
#pragma unroll
                for (int j = 0; j < 4; j++)
#pragma unroll
                    for (int r = 0; r < 4; r++) acc[i][j][r] = 0.f;
        }

        if (iter < 15) {
            __syncthreads();
            commit((iter + 1) & 1);
            __syncthreads();
        }
    }
}

// ---------------------------------------------------------------------------
// Fused edge kernel: per CTA (256 thr, 3 CTAs/SM), 64 edges.
// Phase 1 (two passes, 32-reg acc): Eproj = ea @ [Wf_e|Ws_e] -> Epf / Eps fp16
//   Eps overlays the dead Ast/Bs mma buffers after the final mma pass.
// Phase 2: warp-per-8-edges (independent, unrolled): z = Ph[dst]+Ph[src]+Ep;
//          msg; red.v4 to agg[dst].
// ---------------------------------------------------------------------------
#define TILE_E 64
#define ASTR2 72
#define BSTR2 264
#define EPSTR 136   // halves per Eproj row (per 128-col half)

// layout: Ast [32][72]w @0 (9216B) | Bs [32][264]w @9216 (33792B) -> 43008
//         Epf [64][136]h @43008 (17408B)  -> total 60416
//         Eps [64][136]h @0 (overlay on Ast/Bs after last mma)
#define SMEM_FUSED (43008 + 17408)

__global__ void __launch_bounds__(256, 3)
k_fused(const int* __restrict__ ei, const float* __restrict__ ea,
        const float* __restrict__ Wfe, const float* __restrict__ Wse)
{
    uint32_t* Ast = (uint32_t*)s_raw;                 // [32][ASTR2]
    uint32_t* Bs  = Ast + 32 * ASTR2;                 // [32][BSTR2]
    __half* Epf = (__half*)(s_raw + 43008);           // [64][EPSTR]
    __half* Eps = (__half*)s_raw;                     // [64][EPSTR] (overlay)

    int e0 = blockIdx.x * TILE_E;
    int tid = threadIdx.x, lane = tid & 31, wid = tid >> 5;
    int gid4 = lane >> 2, tig = lane & 3;

    // ---- load A: ea rows transposed -> Ast[k][m] ----
#pragma unroll
    for (int i = 0; i < 2; i++) {
        int id = tid * 2 + i;
        int r = id >> 3, q = (id & 7) * 4;
        float4 v = *(const float4*)(ea + (size_t)(e0 + r) * 32 + q);
        Ast[(q + 0) * ASTR2 + r] = f2tf32(v.x);
        Ast[(q + 1) * ASTR2 + r] = f2tf32(v.y);
        Ast[(q + 2) * ASTR2 + r] = f2tf32(v.z);
        Ast[(q + 3) * ASTR2 + r] = f2tf32(v.w);
    }
    // ---- load B: [32 x 256] = Wf_e | Ws_e ----
#pragma unroll
    for (int i = 0; i < 8; i++) {
        int id = tid + i * 256;
        int kk = id >> 6, n4 = (id & 63) * 4;
        const float* src = (n4 < 128) ? (Wfe + kk * 128 + n4)
                                      : (Wse + kk * 128 + (n4 - 128));
        float4 v = *(const float4*)src;
        uint32_t* d = &Bs[kk * BSTR2 + n4];
        d[0] = f2tf32(v.x); d[1] = f2tf32(v.y);
        d[2] = f2tf32(v.z); d[3] = f2tf32(v.w);
    }
    __syncthreads();

    // ---- mma: two passes of 64x128, K=32; acc = 32 regs ----
    int wm = (wid & 1) * 32, wn = (wid >> 1) * 32;

#pragma unroll
    for (int pass = 0; pass < 2; pass++) {
        float acc[2][4][4];
#pragma unroll
        for (int i = 0; i < 2; i++)
#pragma unroll
            for (int j = 0; j < 4; j++)
#pragma unroll
                for (int r = 0; r < 4; r++) acc[i][j][r] = 0.f;

#pragma unroll
        for (int kk = 0; kk < 32; kk += 8) {
            uint32_t a[2][4], b[4][2];
#pragma unroll
            for (int i = 0; i < 2; i++) {
                int m0 = wm + i * 16 + gid4;
                a[i][0] = Ast[(kk + tig) * ASTR2 + m0];
                a[i][1] = Ast[(kk + tig) * ASTR2 + m0 + 8];
                a[i][2] = Ast[(kk + tig + 4) * ASTR2 + m0];
                a[i][3] = Ast[(kk + tig + 4) * ASTR2 + m0 + 8];
            }
#pragma unroll
            for (int j = 0; j < 4; j++) {
                int n0 = pass * 128 + wn + j * 8 + gid4;
                b[j][0] = Bs[(kk + tig) * BSTR2 + n0];
                b[j][1] = Bs[(kk + tig + 4) * BSTR2 + n0];
            }
#pragma unroll
            for (int i = 0; i < 2; i++)
#pragma unroll
                for (int j = 0; j < 4; j++) mma_tf32(acc[i][j], a[i], b[j]);
        }

        if (pass == 1) __syncthreads();   // all mma reads of Ast/Bs done before Eps overlay

        __half* Ep = (pass == 0) ? Epf : Eps;
#pragma unroll
        for (int j = 0; j < 4; j++) {
            int cl = wn + j * 8 + 2 * tig;
#pragma unroll
            for (int i = 0; i < 2; i++) {
                int row = wm + i * 16 + gid4;
                *(__half2*)&Ep[row * EPSTR + cl] =
                    __floats2half2_rn(acc[i][j][0], acc[i][j][1]);
                *(__half2*)&Ep[(row + 8) * EPSTR + cl] =
                    __floats2half2_rn(acc[i][j][2], acc[i][j][3]);
            }
        }
    }
    __syncthreads();

    // ---- edge phase: warp wid handles edges wid*8 .. wid*8+7 ----
#pragma unroll
    for (int t = 0; t < 8; t++) {
        int el = wid * 8 + t;
        int e = e0 + el;
        int src = ei[e];
        int dst = ei[NE + e];

        const uint2* pd = (const uint2*)(g_Ph + (size_t)dst * 512);
        const uint2* ps = (const uint2*)(g_Ph + (size_t)src * 512);

        uint2 fdu = pd[lane],      sdu = pd[lane + 32];
        uint2 fsu = ps[lane + 64], ssu = ps[lane + 96];

        float2 fd0 = __half22float2(*(__half2*)&fdu.x);
        float2 fd1 = __half22float2(*(__half2*)&fdu.y);
        float2 sd0 = __half22float2(*(__half2*)&sdu.x);
        float2 sd1 = __half22float2(*(__half2*)&sdu.y);
        float2 fs0 = __half22float2(*(__half2*)&fsu.x);
        float2 fs1 = __half22float2(*(__half2*)&fsu.y);
        float2 ss0 = __half22float2(*(__half2*)&ssu.x);
        float2 ss1 = __half22float2(*(__half2*)&ssu.y);

        uint2 euf = *(const uint2*)&Epf[el * EPSTR + lane * 4];
        uint2 eus = *(const uint2*)&Eps[el * EPSTR + lane * 4];
        float2 ef0 = __half22float2(*(__half2*)&euf.x);
        float2 ef1 = __half22float2(*(__half2*)&euf.y);
        float2 es0 = __half22float2(*(__half2*)&eus.x);
        float2 es1 = __half22float2(*(__half2*)&eus.y);

        float zf0 = fd0.x + fs0.x + ef0.x, zf1 = fd0.y + fs0.y + ef0.y;
        float zf2 = fd1.x + fs1.x + ef1.x, zf3 = fd1.y + fs1.y + ef1.y;
        float zs0 = sd0.x + ss0.x + es0.x, zs1 = sd0.y + ss0.y + es0.y;
        float zs2 = sd1.x + ss1.x + es1.x, zs3 = sd1.y + ss1.y + es1.y;

        float m0 = sigmoidf_(zf0) * softplusf_(zs0);
        float m1 = sigmoidf_(zf1) * softplusf_(zs1);
        float m2 = sigmoidf_(zf2) * softplusf_(zs2);
        float m3 = sigmoidf_(zf3) * softplusf_(zs3);

        red4(g_agg + (size_t)dst * HID + lane * 4, m0, m1, m2, m3);
    }
}

// ---------------------------------------------------------------------------
// pool: v = relu(h + agg); atomic sums + counts
// ---------------------------------------------------------------------------
__global__ void k_pool(const int* __restrict__ batch) {
    int idx = blockIdx.x * blockDim.x + threadIdx.x;
    if (idx >= NN * 32) return;
    int n = idx >> 5, q = idx & 31;
    int g = batch[n];
    float4 h = ((float4*)g_h)[idx];
    float4 a = ((float4*)g_agg)[idx];
    float vx = fmaxf(h.x + a.x, 0.f), vy = fmaxf(h.y + a.y, 0.f);
    float vz = fmaxf(h.z + a.z, 0.f), vw = fmaxf(h.w + a.w, 0.f);
    red4(g_pool + (size_t)g * HID + q * 4, vx, vy, vz, vw);
    if (q == 0) atomicAdd(&g_cnt[g], 1.f);
}

// ---------------------------------------------------------------------------
// final
// ---------------------------------------------------------------------------
__global__ void k_final(const float* __restrict__ Wlin, const float* __restrict__ blin,
                        float* __restrict__ out) {
    __shared__ float p[HID];
    int g = blockIdx.x, t = threadIdx.x;
    float c = fmaxf(g_cnt[g], 1.f);
    p[t] = g_pool[g * HID + t] / c;
    __syncthreads();
    float acc = blin[t];
#pragma unroll 8
    for (int k = 0; k < HID; k++) acc += p[k] * Wlin[k * HID + t];
    out[g * HID + t] = acc;
}

// ---------------------------------------------------------------------------
extern "C" void kernel_launch(void* const* d_in, const int* in_sizes, int n_in,
                              void* d_out, int out_size) {
    const int*   x    = (const int*)d_in[0];
    const int*   ei   = (const int*)d_in[1];
    const float* ea   = (const float*)d_in[2];
    const int*   batch= (const int*)d_in[3];
    const float* emb  = (const float*)d_in[4];
    const float* Wlin = (const float*)d_in[17];
    const float* blin = (const float*)d_in[18];

    float* out = (float*)d_out;

    __half* Pp;   cudaGetSymbolAddress((void**)&Pp, g_Ph);
    float*  hp;   cudaGetSymbolAddress((void**)&hp, g_h);
    float*  aggp; cudaGetSymbolAddress((void**)&aggp, g_agg);

    static bool attr_done = false;
    if (!attr_done) {
        cudaFuncSetAttribute(k_fused, cudaFuncAttributeMaxDynamicSharedMemorySize,
                             SMEM_FUSED);
        cudaFuncSetAttribute(k_gemm_all, cudaFuncAttributeMaxDynamicSharedMemorySize,
                             SMEM_GEMM);
        attr_done = true;
    }

    k_init<<<(NN * 32 + 255) / 256, 256>>>(x, emb);

    for (int l = 0; l < 3; l++) {
        const float* Wf = (const float*)d_in[5 + 4 * l];
        const float* bf = (const float*)d_in[6 + 4 * l];
        const float* Ws = (const float*)d_in[7 + 4 * l];
        const float* bs = (const float*)d_in[8 + 4 * l];

        {
            int grid = (NN + 127) / 128;
            k_gemm_all<<<grid, 256, SMEM_GEMM>>>(hp, aggp, (l > 0) ? 1 : 0,
                                                 Wf, Ws, bf, bs, Pp);
        }
        {
            k_fused<<<NE / TILE_E, 256, SMEM_FUSED>>>(ei, ea,
                                                      Wf + 256 * 128, Ws + 256 * 128);
        }
    }

    k_pool<<<(NN * 32 + 255) / 256, 256>>>(batch);
    k_final<<<NG, HID>>>(Wlin, blin, out);

    (void)in_sizes; (void)n_in; (void)out_size;
}

// round 15
// speedup vs baseline: 1.4261x; 1.4261x over previous
#include <cuda_runtime.h>
#include <cuda_fp16.h>
#include <cstdint>
#include <math.h>

#define NN 50000
#define NE 800000
#define HID 128
#define NG 500

// Scratch (device globals: no allocation allowed)
__device__ float g_h[(size_t)NN * HID];
__device__ __half g_Ph[(size_t)NN * 512];       // [Fdst|Sdst|Fsrc|Ssrc] per node (fp16)
__device__ float g_agg[(size_t)NN * HID];
__device__ float g_pool[NG * HID];
__device__ float g_cnt[NG];

// ---------------------------------------------------------------------------
// helpers
// ---------------------------------------------------------------------------
__device__ __forceinline__ uint32_t f2tf32(float x) {
    uint32_t u;
    asm("cvt.rna.tf32.f32 %0, %1;" : "=r"(u) : "f"(x));
    return u;
}

__device__ __forceinline__ void mma_tf32(float c[4], const uint32_t a[4],
                                         const uint32_t b[2]) {
    asm volatile(
        "mma.sync.aligned.m16n8k8.row.col.f32.tf32.tf32.f32 "
        "{%0,%1,%2,%3}, {%4,%5,%6,%7}, {%8,%9}, {%0,%1,%2,%3};"
        : "+f"(c[0]), "+f"(c[1]), "+f"(c[2]), "+f"(c[3])
        : "r"(a[0]), "r"(a[1]), "r"(a[2]), "r"(a[3]), "r"(b[0]), "r"(b[1]));
}

__device__ __forceinline__ float sigmoidf_(float x) {
    return __fdividef(1.f, 1.f + __expf(-x));
}
__device__ __forceinline__ float softplusf_(float x) {
    return fmaxf(x, 0.f) + __logf(1.f + __expf(-fabsf(x)));
}

__device__ __forceinline__ void red4(float* p, float a, float b, float c, float d) {
    asm volatile("red.global.add.v4.f32 [%0], {%1,%2,%3,%4};"
                 :: "l"(p), "f"(a), "f"(b), "f"(c), "f"(d) : "memory");
}

// ---------------------------------------------------------------------------
// init: h = emb[x]; zero agg/pool/cnt
// ---------------------------------------------------------------------------
__global__ void k_init(const int* __restrict__ x, const float* __restrict__ emb) {
    int idx = blockIdx.x * blockDim.x + threadIdx.x;  // over NN*32
    if (idx < NN * 32) {
        int n = idx >> 5, q = idx & 31;
        ((float4*)g_h)[idx] = ((const float4*)emb)[x[n] * 32 + q];
        ((float4*)g_agg)[idx] = make_float4(0.f, 0.f, 0.f, 0.f);
    }
    if (idx < NG * 32) ((float4*)g_pool)[idx] = make_float4(0.f, 0.f, 0.f, 0.f);
    if (idx < NG) g_cnt[idx] = 0.f;
}

// ---------------------------------------------------------------------------
// Node GEMM, all 4 kinds per CTA (tf32 mma, double-buffered B slabs).
// (round-12 version, unchanged)
// ---------------------------------------------------------------------------
#define ASTR3 136
#define BSTR3 136
#define SMEM_GEMM ((128 * ASTR3 + 2 * 32 * BSTR3) * 4)

extern __shared__ unsigned char s_raw[];

__global__ void __launch_bounds__(256, 2)
k_gemm_all(float* __restrict__ Ah, float* __restrict__ Agg, int fuse,
           const float* __restrict__ Wf, const float* __restrict__ Ws,
           const float* __restrict__ bf, const float* __restrict__ bs,
           __half* __restrict__ out)
{
    uint32_t* Ast = (uint32_t*)s_raw;          // [128 m][ASTR3]
    uint32_t* Bs  = Ast + 128 * ASTR3;         // [2][32 k][BSTR3]

    int row0 = blockIdx.x * 128;
    int tid = threadIdx.x;
    int lane = tid & 31, wid = tid >> 5;
    int wm = (wid & 1) * 64, wn = (wid >> 1) * 32;
    int gid4 = lane >> 2, tig = lane & 3;

    float4 pre[4];
    auto fetch = [&](int iter) {
        int kind = iter >> 2, slab = iter & 3;
        const float* W = (kind & 1) ? Ws : Wf;
        const float* base = W + (size_t)(((kind >> 1) ? 128 : 0) + slab * 32) * 128;
#pragma unroll
        for (int i = 0; i < 4; i++) {
            int id = tid + i * 256;
            int kk = id >> 5, c4 = (id & 31) * 4;
            pre[i] = *(const float4*)(base + kk * 128 + c4);
        }
    };
    auto commit = [&](int buf) {
#pragma unroll
        for (int i = 0; i < 4; i++) {
            int id = tid + i * 256;
            int kk = id >> 5, c4 = (id & 31) * 4;
            uint32_t* d = &Bs[(buf * 32 + kk) * BSTR3 + c4];
            d[0] = f2tf32(pre[i].x); d[1] = f2tf32(pre[i].y);
            d[2] = f2tf32(pre[i].z); d[3] = f2tf32(pre[i].w);
        }
    };

    fetch(0);

#pragma unroll
    for (int i = 0; i < 16; i++) {
        int id = tid + i * 256;
        int r = id >> 5, c4 = (id & 31) * 4;
        int gr = row0 + r;
        float4 v = make_float4(0.f, 0.f, 0.f, 0.f);
        if (gr < NN) {
            v = *(const float4*)(Ah + (size_t)gr * HID + c4);
            if (fuse) {
                float4 a = *(const float4*)(Agg + (size_t)gr * HID + c4);
                v.x = fmaxf(v.x + a.x, 0.f);
                v.y = fmaxf(v.y + a.y, 0.f);
                v.z = fmaxf(v.z + a.z, 0.f);
                v.w = fmaxf(v.w + a.w, 0.f);
                *(float4*)(Ah + (size_t)gr * HID + c4) = v;
                *(float4*)(Agg + (size_t)gr * HID + c4) = make_float4(0.f, 0.f, 0.f, 0.f);
            }
        }
        *(uint4*)&Ast[r * ASTR3 + c4] =
            make_uint4(f2tf32(v.x), f2tf32(v.y), f2tf32(v.z), f2tf32(v.w));
    }

    commit(0);
    __syncthreads();

    float acc[4][4][4];
#pragma unroll
    for (int i = 0; i < 4; i++)
#pragma unroll
        for (int j = 0; j < 4; j++)
#pragma unroll
            for (int r = 0; r < 4; r++) acc[i][j][r] = 0.f;

    for (int iter = 0; iter < 16; iter++) {
        if (iter < 15) fetch(iter + 1);
        int buf = iter & 1;
        int kbase = (iter & 3) * 32;

#pragma unroll
        for (int kk = 0; kk < 32; kk += 8) {
            uint32_t a[4][4], b[4][2];
#pragma unroll
            for (int i = 0; i < 4; i++) {
                int m0 = wm + i * 16 + gid4;
                const uint32_t* r0p = &Ast[m0 * ASTR3 + kbase + kk + tig];
                const uint32_t* r1p = &Ast[(m0 + 8) * ASTR3 + kbase + kk + tig];
                a[i][0] = r0p[0];
                a[i][1] = r1p[0];
                a[i][2] = r0p[4];
                a[i][3] = r1p[4];
            }
#pragma unroll
            for (int j = 0; j < 4; j++) {
                int n0 = wn + j * 8 + gid4;
                b[j][0] = Bs[(buf * 32 + kk + tig) * BSTR3 + n0];
                b[j][1] = Bs[(buf * 32 + kk + tig + 4) * BSTR3 + n0];
            }
#pragma unroll
            for (int i = 0; i < 4; i++)
#pragma unroll
                for (int j = 0; j < 4; j++) mma_tf32(acc[i][j], a[i], b[j]);
        }

        if ((iter & 3) == 3) {
            int kind = iter >> 2;
            const float* bias = (kind == 0) ? bf : (kind == 1) ? bs : nullptr;
            int cb = kind * 128;
#pragma unroll
            for (int j = 0; j < 4; j++) {
                int cl = wn + j * 8 + 2 * tig;
                float bx = 0.f, by = 0.f;
                if (bias) { bx = bias[cl]; by = bias[cl + 1]; }
#pragma unroll
                for (int i = 0; i < 4; i++) {
                    int r0 = row0 + wm + i * 16 + gid4;
                    if (r0 < NN)
                        *(__half2*)(out + (size_t)r0 * 512 + cb + cl) =
                            __floats2half2_rn(acc[i][j][0] + bx, acc[i][j][1] + by);
                    if (r0 + 8 < NN)
                        *(__half2*)(out + (size_t)(r0 + 8) * 512 + cb + cl) =
                            __floats2half2_rn(acc[i][j][2] + bx, acc[i][j][3] + by);
                }
            }
#pragma unroll
            for (int i = 0; i < 4; i++)
#pragma unroll
                for (int j = 0; j < 4; j++)
#pragma unroll
                    for (int r = 0; r < 4; r++) acc[i][j][r] = 0.f;
        }

        if (iter < 15) {
            __syncthreads();
            commit((iter + 1) & 1);
            __syncthreads();
        }
    }
}

// ---------------------------------------------------------------------------
// Fused edge kernel (round-12 phase 1; phase 2 with 4-edge gather batching).
// ---------------------------------------------------------------------------
#define TILE_E 64
#define ASTR2 72
#define BSTR2 264
#define ESTR 264

#define SMEM_FUSED (32 * ASTR2 * 4 + 32 * BSTR2 * 4 + TILE_E * ESTR * 2)

__global__ void __launch_bounds__(256, 2)
k_fused(const int* __restrict__ ei, const float* __restrict__ ea,
        const float* __restrict__ Wfe, const float* __restrict__ Wse)
{
    uint32_t* Ast = (uint32_t*)s_raw;                 // [32][ASTR2]
    uint32_t* Bs  = Ast + 32 * ASTR2;                 // [32][BSTR2]
    __half* Ep = (__half*)(Bs + 32 * BSTR2);          // [64][ESTR]

    int e0 = blockIdx.x * TILE_E;
    int tid = threadIdx.x, lane = tid & 31, wid = tid >> 5;
    int gid4 = lane >> 2, tig = lane & 3;

    // ---- load A: ea rows transposed -> Ast[k][m] ----
#pragma unroll
    for (int i = 0; i < 2; i++) {
        int id = tid * 2 + i;
        int r = id >> 3, q = (id & 7) * 4;
        float4 v = *(const float4*)(ea + (size_t)(e0 + r) * 32 + q);
        Ast[(q + 0) * ASTR2 + r] = f2tf32(v.x);
        Ast[(q + 1) * ASTR2 + r] = f2tf32(v.y);
        Ast[(q + 2) * ASTR2 + r] = f2tf32(v.z);
        Ast[(q + 3) * ASTR2 + r] = f2tf32(v.w);
    }
    // ---- load B: [32 x 256] = Wf_e | Ws_e ----
#pragma unroll
    for (int i = 0; i < 8; i++) {
        int id = tid + i * 256;
        int kk = id >> 6, n4 = (id & 63) * 4;
        const float* src = (n4 < 128) ? (Wfe + kk * 128 + n4)
                                      : (Wse + kk * 128 + (n4 - 128));
        float4 v = *(const float4*)src;
        uint32_t* d = &Bs[kk * BSTR2 + n4];
        d[0] = f2tf32(v.x); d[1] = f2tf32(v.y);
        d[2] = f2tf32(v.z); d[3] = f2tf32(v.w);
    }
    __syncthreads();

    // ---- mma: M=64 (2 warp rows), N=256 (4 warp cols of 64), K=32 ----
    {
        int wm = (wid & 1) * 32, wn = (wid >> 1) * 64;
        float acc[2][8][4];
#pragma unroll
        for (int i = 0; i < 2; i++)
#pragma unroll
            for (int j = 0; j < 8; j++)
#pragma unroll
                for (int r = 0; r < 4; r++) acc[i][j][r] = 0.f;

#pragma unroll
        for (int kk = 0; kk < 32; kk += 8) {
            uint32_t a[2][4], b[8][2];
#pragma unroll
            for (int i = 0; i < 2; i++) {
                int m0 = wm + i * 16 + gid4;
                a[i][0] = Ast[(kk + tig) * ASTR2 + m0];
                a[i][1] = Ast[(kk + tig) * ASTR2 + m0 + 8];
                a[i][2] = Ast[(kk + tig + 4) * ASTR2 + m0];
                a[i][3] = Ast[(kk + tig + 4) * ASTR2 + m0 + 8];
            }
#pragma unroll
            for (int j = 0; j < 8; j++) {
                int n0 = wn + j * 8 + gid4;
                b[j][0] = Bs[(kk + tig) * BSTR2 + n0];
                b[j][1] = Bs[(kk + tig + 4) * BSTR2 + n0];
            }
#pragma unroll
            for (int i = 0; i < 2; i++)
#pragma unroll
                for (int j = 0; j < 8; j++) mma_tf32(acc[i][j], a[i], b[j]);
        }

        // write Eproj (fp16x2)
#pragma unroll
        for (int j = 0; j < 8; j++) {
            int cl = wn + j * 8 + 2 * tig;
#pragma unroll
            for (int i = 0; i < 2; i++) {
                int row = wm + i * 16 + gid4;
                *(__half2*)&Ep[row * ESTR + cl] =
                    __floats2half2_rn(acc[i][j][0], acc[i][j][1]);
                *(__half2*)&Ep[(row + 8) * ESTR + cl] =
                    __floats2half2_rn(acc[i][j][2], acc[i][j][3]);
            }
        }
    }
    __syncthreads();

    // ---- edge phase: 2 groups of 4 edges; batch all gathers before compute ----
#pragma unroll
    for (int grp = 0; grp < 2; grp++) {
        int base = wid * 8 + grp * 4;

        int sidx[4], didx[4];
#pragma unroll
        for (int t = 0; t < 4; t++) {
            int e = e0 + base + t;
            sidx[t] = ei[e];
            didx[t] = ei[NE + e];
        }

        uint2 fdu[4], sdu[4], fsu[4], ssu[4], euf[4], eus[4];
#pragma unroll
        for (int t = 0; t < 4; t++) {
            const uint2* pd = (const uint2*)(g_Ph + (size_t)didx[t] * 512);
            const uint2* ps = (const uint2*)(g_Ph + (size_t)sidx[t] * 512);
            fdu[t] = pd[lane];
            sdu[t] = pd[lane + 32];
            fsu[t] = ps[lane + 64];
            ssu[t] = ps[lane + 96];
            euf[t] = *(const uint2*)&Ep[(base + t) * ESTR + lane * 4];
            eus[t] = *(const uint2*)&Ep[(base + t) * ESTR + 128 + lane * 4];
        }

#pragma unroll
        for (int t = 0; t < 4; t++) {
            float2 fd0 = __half22float2(*(__half2*)&fdu[t].x);
            float2 fd1 = __half22float2(*(__half2*)&fdu[t].y);
            float2 sd0 = __half22float2(*(__half2*)&sdu[t].x);
            float2 sd1 = __half22float2(*(__half2*)&sdu[t].y);
            float2 fs0 = __half22float2(*(__half2*)&fsu[t].x);
            float2 fs1 = __half22float2(*(__half2*)&fsu[t].y);
            float2 ss0 = __half22float2(*(__half2*)&ssu[t].x);
            float2 ss1 = __half22float2(*(__half2*)&ssu[t].y);
            float2 ef0 = __half22float2(*(__half2*)&euf[t].x);
            float2 ef1 = __half22float2(*(__half2*)&euf[t].y);
            float2 es0 = __half22float2(*(__half2*)&eus[t].x);
            float2 es1 = __half22float2(*(__half2*)&eus[t].y);

            float zf0 = fd0.x + fs0.x + ef0.x, zf1 = fd0.y + fs0.y + ef0.y;
            float zf2 = fd1.x + fs1.x + ef1.x, zf3 = fd1.y + fs1.y + ef1.y;
            float zs0 = sd0.x + ss0.x + es0.x, zs1 = sd0.y + ss0.y + es0.y;
            float zs2 = sd1.x + ss1.x + es1.x, zs3 = sd1.y + ss1.y + es1.y;

            float m0 = sigmoidf_(zf0) * softplusf_(zs0);
            float m1 = sigmoidf_(zf1) * softplusf_(zs1);
            float m2 = sigmoidf_(zf2) * softplusf_(zs2);
            float m3 = sigmoidf_(zf3) * softplusf_(zs3);

            red4(g_agg + (size_t)didx[t] * HID + lane * 4, m0, m1, m2, m3);
        }
    }
}

// ---------------------------------------------------------------------------
// pool: v = relu(h + agg); atomic sums + counts
// ---------------------------------------------------------------------------
__global__ void k_pool(const int* __restrict__ batch) {
    int idx = blockIdx.x * blockDim.x + threadIdx.x;
    if (idx >= NN * 32) return;
    int n = idx >> 5, q = idx & 31;
    int g = batch[n];
    float4 h = ((float4*)g_h)[idx];
    float4 a = ((float4*)g_agg)[idx];
    float vx = fmaxf(h.x + a.x, 0.f), vy = fmaxf(h.y + a.y, 0.f);
    float vz = fmaxf(h.z + a.z, 0.f), vw = fmaxf(h.w + a.w, 0.f);
    red4(g_pool + (size_t)g * HID + q * 4, vx, vy, vz, vw);
    if (q == 0) atomicAdd(&g_cnt[g], 1.f);
}

// ---------------------------------------------------------------------------
// final
// ---------------------------------------------------------------------------
__global__ void k_final(const float* __restrict__ Wlin, const float* __restrict__ blin,
                        float* __restrict__ out) {
    __shared__ float p[HID];
    int g = blockIdx.x, t = threadIdx.x;
    float c = fmaxf(g_cnt[g], 1.f);
    p[t] = g_pool[g * HID + t] / c;
    __syncthreads();
    float acc = blin[t];
#pragma unroll 8
    for (int k = 0; k < HID; k++) acc += p[k] * Wlin[k * HID + t];
    out[g * HID + t] = acc;
}

// ---------------------------------------------------------------------------
extern "C" void kernel_launch(void* const* d_in, const int* in_sizes, int n_in,
                              void* d_out, int out_size) {
    const int*   x    = (const int*)d_in[0];
    const int*   ei   = (const int*)d_in[1];
    const float* ea   = (const float*)d_in[2];
    const int*   batch= (const int*)d_in[3];
    const float* emb  = (const float*)d_in[4];
    const float* Wlin = (const float*)d_in[17];
    const float* blin = (const float*)d_in[18];

    float* out = (float*)d_out;

    __half* Pp;   cudaGetSymbolAddress((void**)&Pp, g_Ph);
    float*  hp;   cudaGetSymbolAddress((void**)&hp, g_h);
    float*  aggp; cudaGetSymbolAddress((void**)&aggp, g_agg);

    static bool attr_done = false;
    if (!attr_done) {
        cudaFuncSetAttribute(k_fused, cudaFuncAttributeMaxDynamicSharedMemorySize,
                             SMEM_FUSED);
        cudaFuncSetAttribute(k_gemm_all, cudaFuncAttributeMaxDynamicSharedMemorySize,
                             SMEM_GEMM);
        attr_done = true;
    }

    k_init<<<(NN * 32 + 255) / 256, 256>>>(x, emb);

    for (int l = 0; l < 3; l++) {
        const float* Wf = (const float*)d_in[5 + 4 * l];
        const float* bf = (const float*)d_in[6 + 4 * l];
        const float* Ws = (const float*)d_in[7 + 4 * l];
        const float* bs = (const float*)d_in[8 + 4 * l];

        {
            int grid = (NN + 127) / 128;
            k_gemm_all<<<grid, 256, SMEM_GEMM>>>(hp, aggp, (l > 0) ? 1 : 0,
                                                 Wf, Ws, bf, bs, Pp);
        }
        {
            k_fused<<<NE / TILE_E, 256, SMEM_FUSED>>>(ei, ea,
                                                      Wf + 256 * 128, Ws + 256 * 128);
        }
    }

    k_pool<<<(NN * 32 + 255) / 256, 256>>>(batch);
    k_final<<<NG, HID>>>(Wlin, blin, out);

    (void)in_sizes; (void)n_in; (void)out_size;
}

// round 16
// speedup vs baseline: 1.4322x; 1.0043x over previous
#include <cuda_runtime.h>
#include <cuda_fp16.h>
#include <cstdint>
#include <math.h>

#define NN 50000
#define NE 800000
#define HID 128
#define NG 500

// Scratch (device globals: no allocation allowed)
__device__ float g_h[(size_t)NN * HID];
__device__ __half g_Ph[(size_t)NN * 512];       // [Fdst|Sdst|Fsrc|Ssrc] per node (fp16)
__device__ float g_agg[(size_t)NN * HID];
__device__ float g_pool[NG * HID];
__device__ float g_cnt[NG];

// ---------------------------------------------------------------------------
// helpers
// ---------------------------------------------------------------------------
__device__ __forceinline__ uint32_t f2tf32(float x) {
    uint32_t u;
    asm("cvt.rna.tf32.f32 %0, %1;" : "=r"(u) : "f"(x));
    return u;
}

__device__ __forceinline__ void mma_tf32(float c[4], const uint32_t a[4],
                                         const uint32_t b[2]) {
    asm volatile(
        "mma.sync.aligned.m16n8k8.row.col.f32.tf32.tf32.f32 "
        "{%0,%1,%2,%3}, {%4,%5,%6,%7}, {%8,%9}, {%0,%1,%2,%3};"
        : "+f"(c[0]), "+f"(c[1]), "+f"(c[2]), "+f"(c[3])
        : "r"(a[0]), "r"(a[1]), "r"(a[2]), "r"(a[3]), "r"(b[0]), "r"(b[1]));
}

__device__ __forceinline__ float sigmoidf_(float x) {
    return __fdividef(1.f, 1.f + __expf(-x));
}
__device__ __forceinline__ float softplusf_(float x) {
    return fmaxf(x, 0.f) + __logf(1.f + __expf(-fabsf(x)));
}

__device__ __forceinline__ void red4(float* p, float a, float b, float c, float d) {
    asm volatile("red.global.add.v4.f32 [%0], {%1,%2,%3,%4};"
                 :: "l"(p), "f"(a), "f"(b), "f"(c), "f"(d) : "memory");
}

// ---------------------------------------------------------------------------
// init: h = emb[x]; zero agg/pool/cnt
// ---------------------------------------------------------------------------
__global__ void k_init(const int* __restrict__ x, const float* __restrict__ emb) {
    int idx = blockIdx.x * blockDim.x + threadIdx.x;  // over NN*32
    if (idx < NN * 32) {
        int n = idx >> 5, q = idx & 31;
        ((float4*)g_h)[idx] = ((const float4*)emb)[x[n] * 32 + q];
        ((float4*)g_agg)[idx] = make_float4(0.f, 0.f, 0.f, 0.f);
    }
    if (idx < NG * 32) ((float4*)g_pool)[idx] = make_float4(0.f, 0.f, 0.f, 0.f);
    if (idx < NG) g_cnt[idx] = 0.f;
}

// ---------------------------------------------------------------------------
// Node GEMM, all 4 kinds per CTA (tf32 mma, double-buffered B slabs,
// single sync per slab).
// ---------------------------------------------------------------------------
#define ASTR3 136
#define BSTR3 136
#define SMEM_GEMM ((128 * ASTR3 + 2 * 32 * BSTR3) * 4)

extern __shared__ unsigned char s_raw[];

__global__ void __launch_bounds__(256, 2)
k_gemm_all(float* __restrict__ Ah, float* __restrict__ Agg, int fuse,
           const float* __restrict__ Wf, const float* __restrict__ Ws,
           const float* __restrict__ bf, const float* __restrict__ bs,
           __half* __restrict__ out)
{
    uint32_t* Ast = (uint32_t*)s_raw;          // [128 m][ASTR3]
    uint32_t* Bs  = Ast + 128 * ASTR3;         // [2][32 k][BSTR3]

    int row0 = blockIdx.x * 128;
    int tid = threadIdx.x;
    int lane = tid & 31, wid = tid >> 5;
    int wm = (wid & 1) * 64, wn = (wid >> 1) * 32;
    int gid4 = lane >> 2, tig = lane & 3;

    float4 pre[4];
    auto fetch = [&](int iter) {
        int kind = iter >> 2, slab = iter & 3;
        const float* W = (kind & 1) ? Ws : Wf;
        const float* base = W + (size_t)(((kind >> 1) ? 128 : 0) + slab * 32) * 128;
#pragma unroll
        for (int i = 0; i < 4; i++) {
            int id = tid + i * 256;
            int kk = id >> 5, c4 = (id & 31) * 4;
            pre[i] = *(const float4*)(base + kk * 128 + c4);
        }
    };
    auto commit = [&](int buf) {
#pragma unroll
        for (int i = 0; i < 4; i++) {
            int id = tid + i * 256;
            int kk = id >> 5, c4 = (id & 31) * 4;
            uint32_t* d = &Bs[(buf * 32 + kk) * BSTR3 + c4];
            d[0] = f2tf32(pre[i].x); d[1] = f2tf32(pre[i].y);
            d[2] = f2tf32(pre[i].z); d[3] = f2tf32(pre[i].w);
        }
    };

    fetch(0);

#pragma unroll
    for (int i = 0; i < 16; i++) {
        int id = tid + i * 256;
        int r = id >> 5, c4 = (id & 31) * 4;
        int gr = row0 + r;
        float4 v = make_float4(0.f, 0.f, 0.f, 0.f);
        if (gr < NN) {
            v = *(const float4*)(Ah + (size_t)gr * HID + c4);
            if (fuse) {
                float4 a = *(const float4*)(Agg + (size_t)gr * HID + c4);
                v.x = fmaxf(v.x + a.x, 0.f);
                v.y = fmaxf(v.y + a.y, 0.f);
                v.z = fmaxf(v.z + a.z, 0.f);
                v.w = fmaxf(v.w + a.w, 0.f);
                *(float4*)(Ah + (size_t)gr * HID + c4) = v;
                *(float4*)(Agg + (size_t)gr * HID + c4) = make_float4(0.f, 0.f, 0.f, 0.f);
            }
        }
        *(uint4*)&Ast[r * ASTR3 + c4] =
            make_uint4(f2tf32(v.x), f2tf32(v.y), f2tf32(v.z), f2tf32(v.w));
    }

    commit(0);
    __syncthreads();

    float acc[4][4][4];
#pragma unroll
    for (int i = 0; i < 4; i++)
#pragma unroll
        for (int j = 0; j < 4; j++)
#pragma unroll
            for (int r = 0; r < 4; r++) acc[i][j][r] = 0.f;

    for (int iter = 0; iter < 16; iter++) {
        if (iter < 15) fetch(iter + 1);
        int buf = iter & 1;
        int kbase = (iter & 3) * 32;

#pragma unroll
        for (int kk = 0; kk < 32; kk += 8) {
            uint32_t a[4][4], b[4][2];
#pragma unroll
            for (int i = 0; i < 4; i++) {
                int m0 = wm + i * 16 + gid4;
                const uint32_t* r0p = &Ast[m0 * ASTR3 + kbase + kk + tig];
                const uint32_t* r1p = &Ast[(m0 + 8) * ASTR3 + kbase + kk + tig];
                a[i][0] = r0p[0];
                a[i][1] = r1p[0];
                a[i][2] = r0p[4];
                a[i][3] = r1p[4];
            }
#pragma unroll
            for (int j = 0; j < 4; j++) {
                int n0 = wn + j * 8 + gid4;
                b[j][0] = Bs[(buf * 32 + kk + tig) * BSTR3 + n0];
                b[j][1] = Bs[(buf * 32 + kk + tig + 4) * BSTR3 + n0];
            }
#pragma unroll
            for (int i = 0; i < 4; i++)
#pragma unroll
                for (int j = 0; j < 4; j++) mma_tf32(acc[i][j], a[i], b[j]);
        }

        if ((iter & 3) == 3) {
            int kind = iter >> 2;
            const float* bias = (kind == 0) ? bf : (kind == 1) ? bs : nullptr;
            int cb = kind * 128;
#pragma unroll
            for (int j = 0; j < 4; j++) {
                int cl = wn + j * 8 + 2 * tig;
                float bx = 0.f, by = 0.f;
                if (bias) { bx = bias[cl]; by = bias[cl + 1]; }
#pragma unroll
                for (int i = 0; i < 4; i++) {
                    int r0 = row0 + wm + i * 16 + gid4;
                    if (r0 < NN)
                        *(__half2*)(out + (size_t)r0 * 512 + cb + cl) =
                            __floats2half2_rn(acc[i][j][0] + bx, acc[i][j][1] + by);
                    if (r0 + 8 < NN)
                        *(__half2*)(out + (size_t)(r0 + 8) * 512 + cb + cl) =
                            __floats2half2_rn(acc[i][j][2] + bx, acc[i][j][3] + by);
                }
            }
#pragma unroll
            for (int i = 0; i < 4; i++)
#pragma unroll
                for (int j = 0; j < 4; j++)
#pragma unroll
                    for (int r = 0; r < 4; r++) acc[i][j][r] = 0.f;
        }

        if (iter < 15) {
            // single-sync double buffer: commit targets buf^1 whose readers
            // all passed the previous sync; sync once before reading it.
            commit((iter + 1) & 1);
            __syncthreads();
        }
    }
}

// ---------------------------------------------------------------------------
// Fused edge kernel, B-resident sub-tiling: 256 edges/CTA in 4 sub-tiles.
// B ([32k x 256]) loaded ONCE per CTA; per sub-tile: stage A(64 edges),
// mma -> Eproj(fp16 smem), then batched-gather phase 2.
// ---------------------------------------------------------------------------
#define TILE_E 256
#define SUB_E 64
#define ASTR2 72
#define BSTR2 264
#define ESTR 264

#define SMEM_FUSED (32 * ASTR2 * 4 + 32 * BSTR2 * 4 + SUB_E * ESTR * 2)

__global__ void __launch_bounds__(256, 2)
k_fused(const int* __restrict__ ei, const float* __restrict__ ea,
        const float* __restrict__ Wfe, const float* __restrict__ Wse)
{
    uint32_t* Ast = (uint32_t*)s_raw;                 // [32][ASTR2]
    uint32_t* Bs  = Ast + 32 * ASTR2;                 // [32][BSTR2]
    __half* Ep = (__half*)(Bs + 32 * BSTR2);          // [SUB_E][ESTR]

    int tid = threadIdx.x, lane = tid & 31, wid = tid >> 5;
    int gid4 = lane >> 2, tig = lane & 3;

    // ---- load B once: [32 x 256] = Wf_e | Ws_e ----
#pragma unroll
    for (int i = 0; i < 8; i++) {
        int id = tid + i * 256;
        int kk = id >> 6, n4 = (id & 63) * 4;
        const float* src = (n4 < 128) ? (Wfe + kk * 128 + n4)
                                      : (Wse + kk * 128 + (n4 - 128));
        float4 v = *(const float4*)src;
        uint32_t* d = &Bs[kk * BSTR2 + n4];
        d[0] = f2tf32(v.x); d[1] = f2tf32(v.y);
        d[2] = f2tf32(v.z); d[3] = f2tf32(v.w);
    }
    __syncthreads();

    int wm = (wid & 1) * 32, wn = (wid >> 1) * 64;

    for (int sub = 0; sub < 4; sub++) {
        int e0 = blockIdx.x * TILE_E + sub * SUB_E;

        // ---- stage A: ea rows transposed -> Ast[k][m] ----
        // (phase 2 of previous sub never reads Ast; mma readers of Ast passed
        //  the pre-phase-2 sync, so this write is safe without extra sync)
#pragma unroll
        for (int i = 0; i < 2; i++) {
            int id = tid * 2 + i;
            int r = id >> 3, q = (id & 7) * 4;
            float4 v = *(const float4*)(ea + (size_t)(e0 + r) * 32 + q);
            Ast[(q + 0) * ASTR2 + r] = f2tf32(v.x);
            Ast[(q + 1) * ASTR2 + r] = f2tf32(v.y);
            Ast[(q + 2) * ASTR2 + r] = f2tf32(v.z);
            Ast[(q + 3) * ASTR2 + r] = f2tf32(v.w);
        }
        __syncthreads();   // Ast ready; also: all warps done with prev phase-2 Ep reads

        // ---- mma: M=64 (2 warp rows), N=256 (4 warp cols of 64), K=32 ----
        {
            float acc[2][8][4];
#pragma unroll
            for (int i = 0; i < 2; i++)
#pragma unroll
                for (int j = 0; j < 8; j++)
#pragma unroll
                    for (int r = 0; r < 4; r++) acc[i][j][r] = 0.f;

#pragma unroll
            for (int kk = 0; kk < 32; kk += 8) {
                uint32_t a[2][4], b[8][2];
#pragma unroll
                for (int i = 0; i < 2; i++) {
                    int m0 = wm + i * 16 + gid4;
                    a[i][0] = Ast[(kk + tig) * ASTR2 + m0];
                    a[i][1] = Ast[(kk + tig) * ASTR2 + m0 + 8];
                    a[i][2] = Ast[(kk + tig + 4) * ASTR2 + m0];
                    a[i][3] = Ast[(kk + tig + 4) * ASTR2 + m0 + 8];
                }
#pragma unroll
                for (int j = 0; j < 8; j++) {
                    int n0 = wn + j * 8 + gid4;
                    b[j][0] = Bs[(kk + tig) * BSTR2 + n0];
                    b[j][1] = Bs[(kk + tig + 4) * BSTR2 + n0];
                }
#pragma unroll
                for (int i = 0; i < 2; i++)
#pragma unroll
                    for (int j = 0; j < 8; j++) mma_tf32(acc[i][j], a[i], b[j]);
            }

#pragma unroll
            for (int j = 0; j < 8; j++) {
                int cl = wn + j * 8 + 2 * tig;
#pragma unroll
                for (int i = 0; i < 2; i++) {
                    int row = wm + i * 16 + gid4;
                    *(__half2*)&Ep[row * ESTR + cl] =
                        __floats2half2_rn(acc[i][j][0], acc[i][j][1]);
                    *(__half2*)&Ep[(row + 8) * ESTR + cl] =
                        __floats2half2_rn(acc[i][j][2], acc[i][j][3]);
                }
            }
        }
        __syncthreads();   // Eproj ready for phase 2

        // ---- phase 2: 2 groups of 4 edges; batch all gathers before compute ----
#pragma unroll
        for (int grp = 0; grp < 2; grp++) {
            int base = wid * 8 + grp * 4;

            int sidx[4], didx[4];
#pragma unroll
            for (int t = 0; t < 4; t++) {
                int e = e0 + base + t;
                sidx[t] = ei[e];
                didx[t] = ei[NE + e];
            }

            uint2 fdu[4], sdu[4], fsu[4], ssu[4], euf[4], eus[4];
#pragma unroll
            for (int t = 0; t < 4; t++) {
                const uint2* pd = (const uint2*)(g_Ph + (size_t)didx[t] * 512);
                const uint2* ps = (const uint2*)(g_Ph + (size_t)sidx[t] * 512);
                fdu[t] = pd[lane];
                sdu[t] = pd[lane + 32];
                fsu[t] = ps[lane + 64];
                ssu[t] = ps[lane + 96];
                euf[t] = *(const uint2*)&Ep[(base + t) * ESTR + lane * 4];
                eus[t] = *(const uint2*)&Ep[(base + t) * ESTR + 128 + lane * 4];
            }

#pragma unroll
            for (int t = 0; t < 4; t++) {
                float2 fd0 = __half22float2(*(__half2*)&fdu[t].x);
                float2 fd1 = __half22float2(*(__half2*)&fdu[t].y);
                float2 sd0 = __half22float2(*(__half2*)&sdu[t].x);
                float2 sd1 = __half22float2(*(__half2*)&sdu[t].y);
                float2 fs0 = __half22float2(*(__half2*)&fsu[t].x);
                float2 fs1 = __half22float2(*(__half2*)&fsu[t].y);
                float2 ss0 = __half22float2(*(__half2*)&ssu[t].x);
                float2 ss1 = __half22float2(*(__half2*)&ssu[t].y);
                float2 ef0 = __half22float2(*(__half2*)&euf[t].x);
                float2 ef1 = __half22float2(*(__half2*)&euf[t].y);
                float2 es0 = __half22float2(*(__half2*)&eus[t].x);
                float2 es1 = __half22float2(*(__half2*)&eus[t].y);

                float zf0 = fd0.x + fs0.x + ef0.x, zf1 = fd0.y + fs0.y + ef0.y;
                float zf2 = fd1.x + fs1.x + ef1.x, zf3 = fd1.y + fs1.y + ef1.y;
                float zs0 = sd0.x + ss0.x + es0.x, zs1 = sd0.y + ss0.y + es0.y;
                float zs2 = sd1.x + ss1.x + es1.x, zs3 = sd1.y + ss1.y + es1.y;

                float m0 = sigmoidf_(zf0) * softplusf_(zs0);
                float m1 = sigmoidf_(zf1) * softplusf_(zs1);
                float m2 = sigmoidf_(zf2) * softplusf_(zs2);
                float m3 = sigmoidf_(zf3) * softplusf_(zs3);

                red4(g_agg + (size_t)didx[t] * HID + lane * 4, m0, m1, m2, m3);
            }
        }
    }
}

// ---------------------------------------------------------------------------
// pool: v = relu(h + agg); atomic sums + counts
// ---------------------------------------------------------------------------
__global__ void k_pool(const int* __restrict__ batch) {
    int idx = blockIdx.x * blockDim.x + threadIdx.x;
    if (idx >= NN * 32) return;
    int n = idx >> 5, q = idx & 31;
    int g = batch[n];
    float4 h = ((float4*)g_h)[idx];
    float4 a = ((float4*)g_agg)[idx];
    float vx = fmaxf(h.x + a.x, 0.f), vy = fmaxf(h.y + a.y, 0.f);
    float vz = fmaxf(h.z + a.z, 0.f), vw = fmaxf(h.w + a.w, 0.f);
    red4(g_pool + (size_t)g * HID + q * 4, vx, vy, vz, vw);
    if (q == 0) atomicAdd(&g_cnt[g], 1.f);
}

// ---------------------------------------------------------------------------
// final
// ---------------------------------------------------------------------------
__global__ void k_final(const float* __restrict__ Wlin, const float* __restrict__ blin,
                        float* __restrict__ out) {
    __shared__ float p[HID];
    int g = blockIdx.x, t = threadIdx.x;
    float c = fmaxf(g_cnt[g], 1.f);
    p[t] = g_pool[g * HID + t] / c;
    __syncthreads();
    float acc = blin[t];
#pragma unroll 8
    for (int k = 0; k < HID; k++) acc += p[k] * Wlin[k * HID + t];
    out[g * HID + t] = acc;
}

// ---------------------------------------------------------------------------
extern "C" void kernel_launch(void* const* d_in, const int* in_sizes, int n_in,
                              void* d_out, int out_size) {
    const int*   x    = (const int*)d_in[0];
    const int*   ei   = (const int*)d_in[1];
    const float* ea   = (const float*)d_in[2];
    const int*   batch= (const int*)d_in[3];
    const float* emb  = (const float*)d_in[4];
    const float* Wlin = (const float*)d_in[17];
    const float* blin = (const float*)d_in[18];

    float* out = (float*)d_out;

    __half* Pp;   cudaGetSymbolAddress((void**)&Pp, g_Ph);
    float*  hp;   cudaGetSymbolAddress((void**)&hp, g_h);
    float*  aggp; cudaGetSymbolAddress((void**)&aggp, g_agg);

    static bool attr_done = false;
    if (!attr_done) {
        cudaFuncSetAttribute(k_fused, cudaFuncAttributeMaxDynamicSharedMemorySize,
                             SMEM_FUSED);
        cudaFuncSetAttribute(k_gemm_all, cudaFuncAttributeMaxDynamicSharedMemorySize,
                             SMEM_GEMM);
        attr_done = true;
    }

    k_init<<<(NN * 32 + 255) / 256, 256>>>(x, emb);

    for (int l = 0; l < 3; l++) {
        const float* Wf = (const float*)d_in[5 + 4 * l];
        const float* bf = (const float*)d_in[6 + 4 * l];
        const float* Ws = (const float*)d_in[7 + 4 * l];
        const float* bs = (const float*)d_in[8 + 4 * l];

        {
            int grid = (NN + 127) / 128;
            k_gemm_all<<<grid, 256, SMEM_GEMM>>>(hp, aggp, (l > 0) ? 1 : 0,
                                                 Wf, Ws, bf, bs, Pp);
        }
        {
            k_fused<<<NE / TILE_E, 256, SMEM_FUSED>>>(ei, ea,
                                                      Wf + 256 * 128, Ws + 256 * 128);
        }
    }

    k_pool<<<(NN * 32 + 255) / 256, 256>>>(batch);
    k_final<<<NG, HID>>>(Wlin, blin, out);

    (void)in_sizes; (void)n_in; (void)out_size;
}

// round 17
// speedup vs baseline: 1.5457x; 1.0792x over previous
#include <cuda_runtime.h>
#include <cuda_fp16.h>
#include <cstdint>
#include <math.h>

#define NN 50000
#define NE 800000
#define HID 128
#define NG 500

// Scratch (device globals: no allocation allowed)
__device__ float g_h[(size_t)NN * HID];
__device__ __half g_Ph[(size_t)NN * 512];       // [Fdst|Sdst|Fsrc|Ssrc] per node (fp16)
__device__ float g_agg[(size_t)NN * HID];
__device__ float g_pool[NG * HID];
__device__ float g_cnt[NG];

// ---------------------------------------------------------------------------
// helpers
// ---------------------------------------------------------------------------
__device__ __forceinline__ uint32_t f2tf32(float x) {
    uint32_t u;
    asm("cvt.rna.tf32.f32 %0, %1;" : "=r"(u) : "f"(x));
    return u;
}

__device__ __forceinline__ void mma_tf32(float c[4], const uint32_t a[4],
                                         const uint32_t b[2]) {
    asm volatile(
        "mma.sync.aligned.m16n8k8.row.col.f32.tf32.tf32.f32 "
        "{%0,%1,%2,%3}, {%4,%5,%6,%7}, {%8,%9}, {%0,%1,%2,%3};"
        : "+f"(c[0]), "+f"(c[1]), "+f"(c[2]), "+f"(c[3])
        : "r"(a[0]), "r"(a[1]), "r"(a[2]), "r"(a[3]), "r"(b[0]), "r"(b[1]));
}

__device__ __forceinline__ void mma_f16(float c[4], const uint32_t a[4],
                                        const uint32_t b[2]) {
    asm volatile(
        "mma.sync.aligned.m16n8k16.row.col.f32.f16.f16.f32 "
        "{%0,%1,%2,%3}, {%4,%5,%6,%7}, {%8,%9}, {%0,%1,%2,%3};"
        : "+f"(c[0]), "+f"(c[1]), "+f"(c[2]), "+f"(c[3])
        : "r"(a[0]), "r"(a[1]), "r"(a[2]), "r"(a[3]), "r"(b[0]), "r"(b[1]));
}

__device__ __forceinline__ float sigmoidf_(float x) {
    return __fdividef(1.f, 1.f + __expf(-x));
}
__device__ __forceinline__ float softplusf_(float x) {
    return fmaxf(x, 0.f) + __logf(1.f + __expf(-fabsf(x)));
}

__device__ __forceinline__ void red4(float* p, float a, float b, float c, float d) {
    asm volatile("red.global.add.v4.f32 [%0], {%1,%2,%3,%4};"
                 :: "l"(p), "f"(a), "f"(b), "f"(c), "f"(d) : "memory");
}

// ---------------------------------------------------------------------------
// init: h = emb[x]; zero agg/pool/cnt
// ---------------------------------------------------------------------------
__global__ void k_init(const int* __restrict__ x, const float* __restrict__ emb) {
    int idx = blockIdx.x * blockDim.x + threadIdx.x;  // over NN*32
    if (idx < NN * 32) {
        int n = idx >> 5, q = idx & 31;
        ((float4*)g_h)[idx] = ((const float4*)emb)[x[n] * 32 + q];
        ((float4*)g_agg)[idx] = make_float4(0.f, 0.f, 0.f, 0.f);
    }
    if (idx < NG * 32) ((float4*)g_pool)[idx] = make_float4(0.f, 0.f, 0.f, 0.f);
    if (idx < NG) g_cnt[idx] = 0.f;
}

// ---------------------------------------------------------------------------
// Node GEMM, all 4 kinds per CTA — fp16 mma m16n8k16, fp32 accumulate.
// A staged once as half2 (k-pairs contiguous); B streamed in 32-k slabs,
// double-buffered, stored as half2 (k even, k odd) per column.
// ---------------------------------------------------------------------------
#define ASTRH 68    // half2 per A row (64 + 4 pad)
#define BSTRH 136   // half2 per B k2-row (128 + 8 pad)
#define SMEM_GEMM ((128 * ASTRH + 2 * 16 * BSTRH) * 4)   // 52224 B

extern __shared__ unsigned char s_raw[];

__global__ void __launch_bounds__(256, 2)
k_gemm_all(float* __restrict__ Ah, float* __restrict__ Agg, int fuse,
           const float* __restrict__ Wf, const float* __restrict__ Ws,
           const float* __restrict__ bf, const float* __restrict__ bs,
           __half* __restrict__ out)
{
    __half2* Ast2 = (__half2*)s_raw;           // [128 m][ASTRH]
    __half2* Bs2  = Ast2 + 128 * ASTRH;        // [2][16 k2][BSTRH]
    const uint32_t* A32 = (const uint32_t*)Ast2;
    const uint32_t* B32 = (const uint32_t*)Bs2;

    int row0 = blockIdx.x * 128;
    int tid = threadIdx.x;
    int lane = tid & 31, wid = tid >> 5;
    int wm = (wid & 1) * 64, wn = (wid >> 1) * 32;
    int gid4 = lane >> 2, tig = lane & 3;

    // ---- B slab prefetch: 32 k-rows x 128 cols (fp32 in, half2-pair out) ----
    float4 pre[4];
    auto fetch = [&](int iter) {
        int kind = iter >> 2, slab = iter & 3;
        const float* W = (kind & 1) ? Ws : Wf;
        const float* base = W + (size_t)(((kind >> 1) ? 128 : 0) + slab * 32) * 128;
#pragma unroll
        for (int i = 0; i < 2; i++) {
            int id = tid + i * 256;            // 0..511: 16 k2-rows x 32 col-quads
            int kk2 = id >> 5, c4 = (id & 31) * 4;
            pre[2 * i]     = *(const float4*)(base + (2 * kk2)     * 128 + c4);
            pre[2 * i + 1] = *(const float4*)(base + (2 * kk2 + 1) * 128 + c4);
        }
    };
    auto commit = [&](int buf) {
#pragma unroll
        for (int i = 0; i < 2; i++) {
            int id = tid + i * 256;
            int kk2 = id >> 5, c4 = (id & 31) * 4;
            __half2* d = Bs2 + (size_t)(buf * 16 + kk2) * BSTRH + c4;
            d[0] = __floats2half2_rn(pre[2 * i].x, pre[2 * i + 1].x);
            d[1] = __floats2half2_rn(pre[2 * i].y, pre[2 * i + 1].y);
            d[2] = __floats2half2_rn(pre[2 * i].z, pre[2 * i + 1].z);
            d[3] = __floats2half2_rn(pre[2 * i].w, pre[2 * i + 1].w);
        }
    };

    fetch(0);

    // ---- stage A: 128 rows x 128 k as half2; optional fused relu-update ----
#pragma unroll
    for (int i = 0; i < 16; i++) {
        int id = tid + i * 256;                // float4 over 128 rows x 32
        int r = id >> 5, c4 = (id & 31) * 4, c2 = (id & 31) * 2;
        int gr = row0 + r;
        float4 v = make_float4(0.f, 0.f, 0.f, 0.f);
        if (gr < NN) {
            v = *(const float4*)(Ah + (size_t)gr * HID + c4);
            if (fuse) {
                float4 a = *(const float4*)(Agg + (size_t)gr * HID + c4);
                v.x = fmaxf(v.x + a.x, 0.f);
                v.y = fmaxf(v.y + a.y, 0.f);
                v.z = fmaxf(v.z + a.z, 0.f);
                v.w = fmaxf(v.w + a.w, 0.f);
                *(float4*)(Ah + (size_t)gr * HID + c4) = v;
                *(float4*)(Agg + (size_t)gr * HID + c4) = make_float4(0.f, 0.f, 0.f, 0.f);
            }
        }
        __half2* da = Ast2 + (size_t)r * ASTRH + c2;
        da[0] = __floats2half2_rn(v.x, v.y);
        da[1] = __floats2half2_rn(v.z, v.w);
    }

    commit(0);
    __syncthreads();

    float acc[4][4][4];
#pragma unroll
    for (int i = 0; i < 4; i++)
#pragma unroll
        for (int j = 0; j < 4; j++)
#pragma unroll
            for (int r = 0; r < 4; r++) acc[i][j][r] = 0.f;

    for (int iter = 0; iter < 16; iter++) {
        if (iter < 15) fetch(iter + 1);
        int buf = iter & 1;
        int kb2 = (iter & 3) * 16;     // A's half2 k-offset for this 32-k slab

        // two k16 chunks per slab (c = half2 offset within slab)
#pragma unroll
        for (int c = 0; c < 16; c += 8) {
            uint32_t a[4][4], b[4][2];
#pragma unroll
            for (int i = 0; i < 4; i++) {
                int m0 = wm + i * 16 + gid4;
                a[i][0] = A32[(size_t)m0 * ASTRH + kb2 + c + tig];
                a[i][1] = A32[(size_t)(m0 + 8) * ASTRH + kb2 + c + tig];
                a[i][2] = A32[(size_t)m0 * ASTRH + kb2 + c + 4 + tig];
                a[i][3] = A32[(size_t)(m0 + 8) * ASTRH + kb2 + c + 4 + tig];
            }
#pragma unroll
            for (int j = 0; j < 4; j++) {
                int n0 = wn + j * 8 + gid4;
                b[j][0] = B32[(size_t)(buf * 16 + c + tig) * BSTRH + n0];
                b[j][1] = B32[(size_t)(buf * 16 + c + 4 + tig) * BSTRH + n0];
            }
#pragma unroll
            for (int i = 0; i < 4; i++)
#pragma unroll
                for (int j = 0; j < 4; j++) mma_f16(acc[i][j], a[i], b[j]);
        }

        // end of a kind (4 slabs) -> epilogue
        if ((iter & 3) == 3) {
            int kind = iter >> 2;
            const float* bias = (kind == 0) ? bf : (kind == 1) ? bs : nullptr;
            int cb = kind * 128;
#pragma unroll
            for (int j = 0; j < 4; j++) {
                int cl = wn + j * 8 + 2 * tig;
                float bx = 0.f, by = 0.f;
                if (bias) { bx = bias[cl]; by = bias[cl + 1]; }
#pragma unroll
                for (int i = 0; i < 4; i++) {
                    int r0 = row0 + wm + i * 16 + gid4;
                    if (r0 < NN)
                        *(__half2*)(out + (size_t)r0 * 512 + cb + cl) =
                            __floats2half2_rn(acc[i][j][0] + bx, acc[i][j][1] + by);
                    if (r0 + 8 < NN)
                        *(__half2*)(out + (size_t)(r0 + 8) * 512 + cb + cl) =
                            __floats2half2_rn(acc[i][j][2] + bx, acc[i][j][3] + by);
                }
            }
#pragma unroll
            for (int i = 0; i < 4; i++)
#pragma unroll
                for (int j = 0; j < 4; j++)
#pragma unroll
                    for (int r = 0; r < 4; r++) acc[i][j][r] = 0.f;
        }

        if (iter < 15) {
            // single-sync double buffer: commit targets buf^1 whose readers
            // all passed the previous sync; sync once before reading it.
            commit((iter + 1) & 1);
            __syncthreads();
        }
    }
}

// ---------------------------------------------------------------------------
// Fused edge kernel, B-resident sub-tiling: 256 edges/CTA in 4 sub-tiles.
// (round-16 version, unchanged)
// ---------------------------------------------------------------------------
#define TILE_E 256
#define SUB_E 64
#define ASTR2 72
#define BSTR2 264
#define ESTR 264

#define SMEM_FUSED (32 * ASTR2 * 4 + 32 * BSTR2 * 4 + SUB_E * ESTR * 2)

__global__ void __launch_bounds__(256, 2)
k_fused(const int* __restrict__ ei, const float* __restrict__ ea,
        const float* __restrict__ Wfe, const float* __restrict__ Wse)
{
    uint32_t* Ast = (uint32_t*)s_raw;                 // [32][ASTR2]
    uint32_t* Bs  = Ast + 32 * ASTR2;                 // [32][BSTR2]
    __half* Ep = (__half*)(Bs + 32 * BSTR2);          // [SUB_E][ESTR]

    int tid = threadIdx.x, lane = tid & 31, wid = tid >> 5;
    int gid4 = lane >> 2, tig = lane & 3;

    // ---- load B once: [32 x 256] = Wf_e | Ws_e ----
#pragma unroll
    for (int i = 0; i < 8; i++) {
        int id = tid + i * 256;
        int kk = id >> 6, n4 = (id & 63) * 4;
        const float* src = (n4 < 128) ? (Wfe + kk * 128 + n4)
                                      : (Wse + kk * 128 + (n4 - 128));
        float4 v = *(const float4*)src;
        uint32_t* d = &Bs[kk * BSTR2 + n4];
        d[0] = f2tf32(v.x); d[1] = f2tf32(v.y);
        d[2] = f2tf32(v.z); d[3] = f2tf32(v.w);
    }
    __syncthreads();

    int wm = (wid & 1) * 32, wn = (wid >> 1) * 64;

    for (int sub = 0; sub < 4; sub++) {
        int e0 = blockIdx.x * TILE_E + sub * SUB_E;

        // ---- stage A: ea rows transposed -> Ast[k][m] ----
#pragma unroll
        for (int i = 0; i < 2; i++) {
            int id = tid * 2 + i;
            int r = id >> 3, q = (id & 7) * 4;
            float4 v = *(const float4*)(ea + (size_t)(e0 + r) * 32 + q);
            Ast[(q + 0) * ASTR2 + r] = f2tf32(v.x);
            Ast[(q + 1) * ASTR2 + r] = f2tf32(v.y);
            Ast[(q + 2) * ASTR2 + r] = f2tf32(v.z);
            Ast[(q + 3) * ASTR2 + r] = f2tf32(v.w);
        }
        __syncthreads();   // Ast ready; prev phase-2 Ep reads done

        // ---- mma: M=64, N=256, K=32 ----
        {
            float acc[2][8][4];
#pragma unroll
            for (int i = 0; i < 2; i++)
#pragma unroll
                for (int j = 0; j < 8; j++)
#pragma unroll
                    for (int r = 0; r < 4; r++) acc[i][j][r] = 0.f;

#pragma unroll
            for (int kk = 0; kk < 32; kk += 8) {
                uint32_t a[2][4], b[8][2];
#pragma unroll
                for (int i = 0; i < 2; i++) {
                    int m0 = wm + i * 16 + gid4;
                    a[i][0] = Ast[(kk + tig) * ASTR2 + m0];
                    a[i][1] = Ast[(kk + tig) * ASTR2 + m0 + 8];
                    a[i][2] = Ast[(kk + tig + 4) * ASTR2 + m0];
                    a[i][3] = Ast[(kk + tig + 4) * ASTR2 + m0 + 8];
                }
#pragma unroll
                for (int j = 0; j < 8; j++) {
                    int n0 = wn + j * 8 + gid4;
                    b[j][0] = Bs[(kk + tig) * BSTR2 + n0];
                    b[j][1] = Bs[(kk + tig + 4) * BSTR2 + n0];
                }
#pragma unroll
                for (int i = 0; i < 2; i++)
#pragma unroll
                    for (int j = 0; j < 8; j++) mma_tf32(acc[i][j], a[i], b[j]);
            }

#pragma unroll
            for (int j = 0; j < 8; j++) {
                int cl = wn + j * 8 + 2 * tig;
#pragma unroll
                for (int i = 0; i < 2; i++) {
                    int row = wm + i * 16 + gid4;
                    *(__half2*)&Ep[row * ESTR + cl] =
                        __floats2half2_rn(acc[i][j][0], acc[i][j][1]);
                    *(__half2*)&Ep[(row + 8) * ESTR + cl] =
                        __floats2half2_rn(acc[i][j][2], acc[i][j][3]);
                }
            }
        }
        __syncthreads();   // Eproj ready for phase 2

        // ---- phase 2: 2 groups of 4 edges; batch all gathers before compute ----
#pragma unroll
        for (int grp = 0; grp < 2; grp++) {
            int base = wid * 8 + grp * 4;

            int sidx[4], didx[4];
#pragma unroll
            for (int t = 0; t < 4; t++) {
                int e = e0 + base + t;
                sidx[t] = ei[e];
                didx[t] = ei[NE + e];
            }

            uint2 fdu[4], sdu[4], fsu[4], ssu[4], euf[4], eus[4];
#pragma unroll
            for (int t = 0; t < 4; t++) {
                const uint2* pd = (const uint2*)(g_Ph + (size_t)didx[t] * 512);
                const uint2* ps = (const uint2*)(g_Ph + (size_t)sidx[t] * 512);
                fdu[t] = pd[lane];
                sdu[t] = pd[lane + 32];
                fsu[t] = ps[lane + 64];
                ssu[t] = ps[lane + 96];
                euf[t] = *(const uint2*)&Ep[(base + t) * ESTR + lane * 4];
                eus[t] = *(const uint2*)&Ep[(base + t) * ESTR + 128 + lane * 4];
            }

#pragma unroll
            for (int t = 0; t < 4; t++) {
                float2 fd0 = __half22float2(*(__half2*)&fdu[t].x);
                float2 fd1 = __half22float2(*(__half2*)&fdu[t].y);
                float2 sd0 = __half22float2(*(__half2*)&sdu[t].x);
                float2 sd1 = __half22float2(*(__half2*)&sdu[t].y);
                float2 fs0 = __half22float2(*(__half2*)&fsu[t].x);
                float2 fs1 = __half22float2(*(__half2*)&fsu[t].y);
                float2 ss0 = __half22float2(*(__half2*)&ssu[t].x);
                float2 ss1 = __half22float2(*(__half2*)&ssu[t].y);
                float2 ef0 = __half22float2(*(__half2*)&euf[t].x);
                float2 ef1 = __half22float2(*(__half2*)&euf[t].y);
                float2 es0 = __half22float2(*(__half2*)&eus[t].x);
                float2 es1 = __half22float2(*(__half2*)&eus[t].y);

                float zf0 = fd0.x + fs0.x + ef0.x, zf1 = fd0.y + fs0.y + ef0.y;
                float zf2 = fd1.x + fs1.x + ef1.x, zf3 = fd1.y + fs1.y + ef1.y;
                float zs0 = sd0.x + ss0.x + es0.x, zs1 = sd0.y + ss0.y + es0.y;
                float zs2 = sd1.x + ss1.x + es1.x, zs3 = sd1.y + ss1.y + es1.y;

                float m0 = sigmoidf_(zf0) * softplusf_(zs0);
                float m1 = sigmoidf_(zf1) * softplusf_(zs1);
                float m2 = sigmoidf_(zf2) * softplusf_(zs2);
                float m3 = sigmoidf_(zf3) * softplusf_(zs3);

                red4(g_agg + (size_t)didx[t] * HID + lane * 4, m0, m1, m2, m3);
            }
        }
    }
}

// ---------------------------------------------------------------------------
// pool: v = relu(h + agg); atomic sums + counts
// ---------------------------------------------------------------------------
__global__ void k_pool(const int* __restrict__ batch) {
    int idx = blockIdx.x * blockDim.x + threadIdx.x;
    if (idx >= NN * 32) return;
    int n = idx >> 5, q = idx & 31;
    int g = batch[n];
    float4 h = ((float4*)g_h)[idx];
    float4 a = ((float4*)g_agg)[idx];
    float vx = fmaxf(h.x + a.x, 0.f), vy = fmaxf(h.y + a.y, 0.f);
    float vz = fmaxf(h.z + a.z, 0.f), vw = fmaxf(h.w + a.w, 0.f);
    red4(g_pool + (size_t)g * HID + q * 4, vx, vy, vz, vw);
    if (q == 0) atomicAdd(&g_cnt[g], 1.f);
}

// ---------------------------------------------------------------------------
// final
// ---------------------------------------------------------------------------
__global__ void k_final(const float* __restrict__ Wlin, const float* __restrict__ blin,
                        float* __restrict__ out) {
    __shared__ float p[HID];
    int g = blockIdx.x, t = threadIdx.x;
    float c = fmaxf(g_cnt[g], 1.f);
    p[t] = g_pool[g * HID + t] / c;
    __syncthreads();
    float acc = blin[t];
#pragma unroll 8
    for (int k = 0; k < HID; k++) acc += p[k] * Wlin[k * HID + t];
    out[g * HID + t] = acc;
}

// ---------------------------------------------------------------------------
extern "C" void kernel_launch(void* const* d_in, const int* in_sizes, int n_in,
                              void* d_out, int out_size) {
    const int*   x    = (const int*)d_in[0];
    const int*   ei   = (const int*)d_in[1];
    const float* ea   = (const float*)d_in[2];
    const int*   batch= (const int*)d_in[3];
    const float* emb  = (const float*)d_in[4];
    const float* Wlin = (const float*)d_in[17];
    const float* blin = (const float*)d_in[18];

    float* out = (float*)d_out;

    __half* Pp;   cudaGetSymbolAddress((void**)&Pp, g_Ph);
    float*  hp;   cudaGetSymbolAddress((void**)&hp, g_h);
    float*  aggp; cudaGetSymbolAddress((void**)&aggp, g_agg);

    static bool attr_done = false;
    if (!attr_done) {
        cudaFuncSetAttribute(k_fused, cudaFuncAttributeMaxDynamicSharedMemorySize,
                             SMEM_FUSED);
        cudaFuncSetAttribute(k_gemm_all, cudaFuncAttributeMaxDynamicSharedMemorySize,
                             SMEM_GEMM);
        attr_done = true;
    }

    k_init<<<(NN * 32 + 255) / 256, 256>>>(x, emb);

    for (int l = 0; l < 3; l++) {
        const float* Wf = (const float*)d_in[5 + 4 * l];
        const float* bf = (const float*)d_in[6 + 4 * l];
        const float* Ws = (const float*)d_in[7 + 4 * l];
        const float* bs = (const float*)d_in[8 + 4 * l];

        {
            int grid = (NN + 127) / 128;
            k_gemm_all<<<grid, 256, SMEM_GEMM>>>(hp, aggp, (l > 0) ? 1 : 0,
                                                 Wf, Ws, bf, bs, Pp);
        }
        {
            k_fused<<<NE / TILE_E, 256, SMEM_FUSED>>>(ei, ea,
                                                      Wf + 256 * 128, Ws + 256 * 128);
        }
    }

    k_pool<<<(NN * 32 + 255) / 256, 256>>>(batch);
    k_final<<<NG, HID>>>(Wlin, blin, out);

    (void)in_sizes; (void)n_in; (void)out_size;
}